// round 3
// baseline (speedup 1.0000x reference)
#include <cuda_runtime.h>
#include <stdint.h>

// ConvLSTMSNN — exact dead-code-eliminated form (see R2 proof: spk1/2/3 == 0
// identically under fp32 semantics, so the output depends only on the two
// Leaky layers driven by the constant fb1; batch dimension is a broadcast).
//
// R3: phase-split to remove SHFLs from the recurrence critical path.
//   P1: 128 threads run mem4 per-dim recurrence; ballot-transpose spike bits.
//   P2: 100 threads compute fc2(t) via nibble subset-sum LUT.
//   P3: 2 threads run mem5 recurrence.
//   P4: 128 threads broadcast-write the output.
// Threshold test uses fmaf(m,1e10f,-1e10f): the product m*1e10 is exact inside
// the FMA, so the single-rounded result has exactly the sign of (m - 1.0f).
// reset_{t+1} == spk_t (same predicate on the same mem value), so the spike
// float doubles as next step's reset.

#define TT 100

__global__ void __launch_bounds__(128)
snn_head_kernel(const float* __restrict__ fb1,
                const float* __restrict__ fw2,
                const float* __restrict__ fb2,
                float* __restrict__ out)
{
    __shared__ uint32_t tb[TT * 4];   // tb[t*4+w]: spike bits of dims 32w..32w+31 at step t
    __shared__ float2   lut[512];     // lut[g*16+nib] = (sum w0, sum w1) over nibble subset
    __shared__ float2   scur[TT];     // fc2 pre-activations per t
    __shared__ float4   sres[TT];     // (spk0, spk1, mem0, mem1) per t

    const int tid  = threadIdx.x;
    const int lane = tid & 31;
    const int wid  = tid >> 5;

    // ---- LUT build (parallel, from global fw2; no sync needed before P1) ----
    {
        const int g  = tid >> 2;          // group of 4 dims: d = 4g..4g+3
        const int nb = (tid & 3) << 2;    // this thread builds nibbles nb..nb+3
        const float wa0 = fw2[4*g+0], wa1 = fw2[4*g+1], wa2 = fw2[4*g+2], wa3 = fw2[4*g+3];
        const float wb0 = fw2[128+4*g+0], wb1 = fw2[128+4*g+1],
                    wb2 = fw2[128+4*g+2], wb3 = fw2[128+4*g+3];
        #pragma unroll
        for (int k = 0; k < 4; k++) {
            const int n = nb + k;
            float s0 = 0.f, s1 = 0.f;
            if (n & 1) { s0 += wa0; s1 += wb0; }
            if (n & 2) { s0 += wa1; s1 += wb1; }
            if (n & 4) { s0 += wa2; s1 += wb2; }
            if (n & 8) { s0 += wa3; s1 += wb3; }
            lut[g*16 + n] = make_float2(s0, s1);
        }
    }

    // ---- Phase 1: mem4 recurrence, one dim per thread; ballot-transpose spikes ----
    {
        const float b = fb1[tid];
        float m = 0.f, sprev = 0.f;       // sprev = spk_{t-1} = reset_t
        #pragma unroll 4
        for (int t = 0; t < TT; t++) {
            m = fmaf(0.9f, m, b) - sprev;                 // mem_t
            const float e = fmaf(m, 1e10f, -1e10f);       // sign == sign(m-1), exact
            sprev = fminf(fmaxf(e, 0.f), 1.f);            // spk_t in {0,1}
            const unsigned mask = __ballot_sync(0xffffffffu, e > 0.f);
            if (lane == (t & 31)) tb[t*4 + wid] = mask;
        }
    }
    __syncthreads();

    // ---- Phase 2: fc2(t) via nibble LUT, one t per thread ----
    if (tid < TT) {
        const uint4 w4 = *(const uint4*)(tb + tid*4);
        const uint32_t ww[4] = { w4.x, w4.y, w4.z, w4.w };
        float v0 = 0.f, v1 = 0.f;
        #pragma unroll
        for (int wd = 0; wd < 4; wd++) {
            const uint32_t word = ww[wd];
            #pragma unroll
            for (int q = 0; q < 8; q++) {
                const int nib = (word >> (q*4)) & 15;
                const float2 e = lut[(wd*8 + q)*16 + nib];
                v0 += e.x; v1 += e.y;
            }
        }
        scur[tid] = make_float2(v0 + fb2[0], v1 + fb2[1]);
    }
    __syncthreads();

    // ---- Phase 3: mem5 recurrence, one output dim per thread (2 threads) ----
    if (tid < 2) {
        float m = 0.f, sp = 0.f;
        #pragma unroll 4
        for (int t = 0; t < TT; t++) {
            const float c = ((const float*)&scur[t])[tid];
            m = fmaf(0.9f, m, c) - sp;
            const float e = fmaf(m, 1e10f, -1e10f);
            sp = fminf(fmaxf(e, 0.f), 1.f);
            ((float*)&sres[t])[tid]     = sp;   // spk
            ((float*)&sres[t])[2 + tid] = m;    // mem
        }
    }
    __syncthreads();

    // ---- Phase 4: broadcast across batch; out = [spk_rec | mem_rec], each [T,64,2] ----
    // float4 index i covers out floats 4i..4i+3; i = half*3200 + t*32 + q.
    #pragma unroll 2
    for (int i = tid; i < 6400; i += 128) {
        const int half = (i >= 3200);
        const int r = i - half*3200;
        const int t = r >> 5;
        const float4 sr = sres[t];
        const float4 val = half ? make_float4(sr.z, sr.w, sr.z, sr.w)
                                : make_float4(sr.x, sr.y, sr.x, sr.y);
        ((float4*)out)[i] = val;
    }
}

extern "C" void kernel_launch(void* const* d_in, const int* in_sizes, int n_in,
                              void* d_out, int out_size)
{
    // inputs (metadata order): x, w1, b1, w2, b2, w3, b3, fw1, fb1, fw2, fb2
    const float* fb1 = (const float*)d_in[8];
    const float* fw2 = (const float*)d_in[9];
    const float* fb2 = (const float*)d_in[10];
    float* out = (float*)d_out;

    snn_head_kernel<<<1, 128>>>(fb1, fw2, fb2, out);
}

// round 4
// speedup vs baseline: 1.0269x; 1.0269x over previous
#include <cuda_runtime.h>
#include <stdint.h>

// ConvLSTMSNN — exact dead-code-eliminated form (R2 proof: under fp32
// semantics of the reference, mem<=1.0 for all conv-LSTM layers, pooled
// values <=1.0, and strict '>' threshold => spk1/2/3 == 0 identically).
// Output depends only on the two Leaky layers driven by constant fb1;
// the batch dimension is a broadcast.
//
// R4: cycle-count attack on all phases.
//  P1 (warps 0-3): mem4 recurrence, 1 dim/thread, FSETP/FSEL spike (12cyc chain),
//     ballot-transpose spike bits. Concurrently warps 4-7 build a byte-subset-sum
//     LUT for fc2 (16 groups x 256 entries, float2).
//  P2 (100 threads): fc2(t) = 16 LDS.64 lookups, 4 independent accumulators.
//  P3 (2 threads): mem5 recurrence.
//  P4 (256 threads): broadcast store, 25 STG.128/thread.

#define TT 100

__global__ void __launch_bounds__(256)
snn_head_kernel(const float* __restrict__ fb1,
                const float* __restrict__ fw2,
                const float* __restrict__ fb2,
                float* __restrict__ out)
{
    __shared__ __align__(16) float2   lut[16 * 256];  // 32 KB: byte subset sums
    __shared__ __align__(16) uint32_t tb[TT * 4];     // spike bits per (t, 32-dim word)
    __shared__ __align__(16) float2   scur[TT];       // fc2 pre-activations per t
    __shared__ __align__(16) float4   sres[TT];       // (spk0,spk1,mem0,mem1) per t

    const int tid = threadIdx.x;

    // hoist fb2 (off the P2 critical path)
    const float fb2_0 = fb2[0];
    const float fb2_1 = fb2[1];

    if (tid < 128) {
        // ---- P1: mem4 recurrence; reset_{t+1} == spk_t (same predicate) ----
        const int lane = tid & 31, wid = tid >> 5;
        const float b = fb1[tid];
        float m = 0.f, s = 0.f;
        #pragma unroll 5
        for (int t = 0; t < TT; t++) {
            m = fmaf(0.9f, m, b) - s;              // mem_t
            const bool p = (m > 1.0f);             // spk_t / reset_{t+1}
            s = p ? 1.0f : 0.0f;
            const unsigned msk = __ballot_sync(0xffffffffu, p);
            if (lane == (t & 31)) tb[t * 4 + wid] = msk;
        }
    } else {
        // ---- LUT build (concurrent with P1): group g covers dims 8g..8g+7 ----
        const int u = tid - 128;      // 0..127
        const int g = u >> 3;         // 16 groups, 8 threads per group
        const int e0 = (u & 7) << 5;  // 32 entries per thread
        float w0[8], w1[8];
        #pragma unroll
        for (int i = 0; i < 8; i++) {
            w0[i] = fw2[g * 8 + i];
            w1[i] = fw2[128 + g * 8 + i];
        }
        #pragma unroll 4
        for (int e = e0; e < e0 + 32; e++) {
            float s0 = 0.f, s1 = 0.f;
            #pragma unroll
            for (int i = 0; i < 8; i++) {
                if (e & (1 << i)) { s0 += w0[i]; s1 += w1[i]; }
            }
            lut[g * 256 + e] = make_float2(s0, s1);
        }
    }
    __syncthreads();

    // ---- P2: fc2(t), one t per thread; 16 byte lookups, 4 accumulators ----
    if (tid < TT) {
        const uint4 w4 = *(const uint4*)(tb + tid * 4);
        const uint32_t ww[4] = { w4.x, w4.y, w4.z, w4.w };
        float x0 = 0.f, x1 = 0.f, y0 = 0.f, y1 = 0.f;
        #pragma unroll
        for (int wd = 0; wd < 4; wd++) {
            const uint32_t v = ww[wd];
            const float2 e0 = lut[(wd * 4 + 0) * 256 + (v & 255)];
            const float2 e1 = lut[(wd * 4 + 1) * 256 + ((v >> 8) & 255)];
            const float2 e2 = lut[(wd * 4 + 2) * 256 + ((v >> 16) & 255)];
            const float2 e3 = lut[(wd * 4 + 3) * 256 + (v >> 24)];
            x0 += e0.x + e1.x;  y0 += e2.x + e3.x;
            x1 += e0.y + e1.y;  y1 += e2.y + e3.y;
        }
        scur[tid] = make_float2(x0 + y0 + fb2_0, x1 + y1 + fb2_1);
    }
    __syncthreads();

    // ---- P3: mem5 recurrence, one output dim per thread ----
    if (tid < 2) {
        float m = 0.f, s = 0.f;
        #pragma unroll 5
        for (int t = 0; t < TT; t++) {
            const float c = ((const float*)&scur[t])[tid];
            m = fmaf(0.9f, m, c) - s;
            const bool p = (m > 1.0f);
            s = p ? 1.0f : 0.0f;
            ((float*)&sres[t])[tid]     = s;   // spk
            ((float*)&sres[t])[2 + tid] = m;   // mem
        }
    }
    __syncthreads();

    // ---- P4: broadcast across batch; out = [spk_rec | mem_rec], each [T,64,2] ----
    #pragma unroll
    for (int k = 0; k < 25; k++) {
        const int i = k * 256 + tid;           // float4 index, 0..6399
        const int half = (i >= 3200);
        const int r = i - half * 3200;
        const int t = r >> 5;
        const float4 sr = sres[t];
        ((float4*)out)[i] = half ? make_float4(sr.z, sr.w, sr.z, sr.w)
                                 : make_float4(sr.x, sr.y, sr.x, sr.y);
    }
}

extern "C" void kernel_launch(void* const* d_in, const int* in_sizes, int n_in,
                              void* d_out, int out_size)
{
    // inputs (metadata order): x, w1, b1, w2, b2, w3, b3, fw1, fb1, fw2, fb2
    const float* fb1 = (const float*)d_in[8];
    const float* fw2 = (const float*)d_in[9];
    const float* fb2 = (const float*)d_in[10];
    float* out = (float*)d_out;

    snn_head_kernel<<<1, 256>>>(fb1, fw2, fb2, out);
}